// round 9
// baseline (speedup 1.0000x reference)
#include <cuda_runtime.h>
#include <cstdint>

#define NN   50000
#define BB   2
#define FIN  128
#define FOUT 64
#define OC   128          // B*FOUT = gather row width
#define EE   800000
#define ROWS (BB * NN)    // 100000

#define WPAD 130          // padded f-stride for transposed W (conflict-free LDS.64)
#define WSM_BYTES (OC * WPAD * 4)   // 66560

// Scratch (allocation-free rule: __device__ globals)
__device__ float g_xt[NN * OC];   // x@W laid out as (n, b*FOUT + o)  -- gather source
__device__ int   g_cnt[NN];       // per-row edge count
__device__ int   g_off[NN];       // CSR row offsets (exclusive)
__device__ int   g_fill[NN];      // fill cursors for permutation
__device__ int   g_col[EE];       // CSR-ordered source columns
__device__ float g_val[EE];       // CSR-ordered edge values

// ---------------------------------------------------------------------------
// Fused GEMM v3: R6 shape (128 thr, warp=8 rows, x via broadcast LDG.128)
// + R7 math (f-paired fp32x2, transposed-W smem, zero packing movs).
// Lane owns 4 columns {lane, 32+lane, 64+lane, 96+lane}; each 64-bit acc holds
// {sum over even f, sum over odd f} for one column; folded at the end.
// ---------------------------------------------------------------------------
__global__ __launch_bounds__(128) void gemm_kernel(
    const float* __restrict__ x, const float* __restrict__ W,
    const float* __restrict__ Wself, const float* __restrict__ bself,
    float* __restrict__ out)
{
    extern __shared__ float wsT[];   // wsT[c*WPAD + f], c<64 -> W, c>=64 -> Wself
    int t = threadIdx.x;
    for (int idx = t; idx < FIN * OC; idx += 128) {
        int f = idx >> 7, c = idx & 127;
        float v = (c < 64) ? W[(f << 6) + c] : Wself[(f << 6) + (c - 64)];
        wsT[c * WPAD + f] = v;
    }
    __syncthreads();

    const int lane = t & 31;
    long warp = (long)blockIdx.x * 4 + (t >> 5);
    long r0 = warp << 3;                       // 8 consecutive rows, same b
    const float* xp = x + r0 * FIN;

    unsigned long long acc[8][4];
    #pragma unroll
    for (int i = 0; i < 8; i++)
        #pragma unroll
        for (int k = 0; k < 4; k++) acc[i][k] = 0ull;

    const float* w0p = wsT + (0 * 32 + lane) * WPAD;
    const float* w1p = wsT + (1 * 32 + lane) * WPAD;
    const float* w2p = wsT + (2 * 32 + lane) * WPAD;
    const float* w3p = wsT + (3 * 32 + lane) * WPAD;

    for (int f = 0; f < FIN; f += 4) {
        ulonglong2 xq[8];                      // two packed f-pairs per row, no movs
        #pragma unroll
        for (int i = 0; i < 8; i++)
            xq[i] = *(const ulonglong2*)(xp + i * FIN + f);   // broadcast LDG.128

        unsigned long long wA[4], wB[4];       // per-col packed f-pairs (LDS.64)
        wA[0] = *(const unsigned long long*)(w0p + f);
        wA[1] = *(const unsigned long long*)(w1p + f);
        wA[2] = *(const unsigned long long*)(w2p + f);
        wA[3] = *(const unsigned long long*)(w3p + f);
        wB[0] = *(const unsigned long long*)(w0p + f + 2);
        wB[1] = *(const unsigned long long*)(w1p + f + 2);
        wB[2] = *(const unsigned long long*)(w2p + f + 2);
        wB[3] = *(const unsigned long long*)(w3p + f + 2);

        #pragma unroll
        for (int i = 0; i < 8; i++) {
            #pragma unroll
            for (int k = 0; k < 4; k++) {
                asm("fma.rn.f32x2 %0, %1, %2, %0;" : "+l"(acc[i][k]) : "l"(xq[i].x), "l"(wA[k]));
                asm("fma.rn.f32x2 %0, %1, %2, %0;" : "+l"(acc[i][k]) : "l"(xq[i].y), "l"(wB[k]));
            }
        }
    }

    int b  = (int)(r0 / NN);
    int n0 = (int)(r0 % NN);
    const float bias2 = bself[lane];
    const float bias3 = bself[32 + lane];
    #pragma unroll
    for (int i = 0; i < 8; i++) {
        int n = n0 + i;
        float s[4];
        #pragma unroll
        for (int k = 0; k < 4; k++) {
            float lo, hi;
            asm("mov.b64 {%0, %1}, %2;" : "=f"(lo), "=f"(hi) : "l"(acc[i][k]));
            s[k] = lo + hi;
        }
        float* xtp = g_xt + (long)n * OC + b * FOUT;
        xtp[lane]      = s[0];                 // W path -> gather source
        xtp[32 + lane] = s[1];
        float* op = out + ((long)b * NN + n) * FOUT;
        op[lane]      = s[2] + bias2;          // self path + bias
        op[32 + lane] = s[3] + bias3;
    }
}

// ---------------------------------------------------------------------------
// CSR build step 1: histogram of destination rows.
// ---------------------------------------------------------------------------
__global__ __launch_bounds__(256) void hist_kernel(const int* __restrict__ erow)
{
    int e = blockIdx.x * 256 + threadIdx.x;          // EE/256 = 3125 blocks, exact
    atomicAdd(&g_cnt[erow[e]], 1);
}

// ---------------------------------------------------------------------------
// CSR build step 2: single-block exclusive scan over 50000 counts.
// ---------------------------------------------------------------------------
#define SCAN_T 1024
#define SEG 49      // 1024*49 = 50176 >= NN
__global__ __launch_bounds__(SCAN_T) void scan_kernel()
{
    __shared__ int ssum[SCAN_T];
    int t = threadIdx.x;
    int base = t * SEG;
    int s = 0;
    for (int i = 0; i < SEG; i++) {
        int idx = base + i;
        if (idx < NN) s += g_cnt[idx];
    }
    ssum[t] = s;
    __syncthreads();
    for (int d = 1; d < SCAN_T; d <<= 1) {
        int v = (t >= d) ? ssum[t - d] : 0;
        __syncthreads();
        ssum[t] += v;
        __syncthreads();
    }
    int run = (t > 0) ? ssum[t - 1] : 0;
    for (int i = 0; i < SEG; i++) {
        int idx = base + i;
        if (idx >= NN) break;
        g_off[idx]  = run;
        g_fill[idx] = run;
        run += g_cnt[idx];
    }
}

// ---------------------------------------------------------------------------
// CSR build step 3: permute (col, val) into CSR order.
// ---------------------------------------------------------------------------
__global__ __launch_bounds__(256) void fill_kernel(
    const int* __restrict__ erow, const int* __restrict__ ecol,
    const float* __restrict__ eval)
{
    int e = blockIdx.x * 256 + threadIdx.x;
    int pos = atomicAdd(&g_fill[erow[e]], 1);
    g_col[pos] = ecol[e];
    g_val[pos] = eval[e];
}

// ---------------------------------------------------------------------------
// Pull-mode gather + fused epilogue. Warp per destination row n.
// ---------------------------------------------------------------------------
__global__ __launch_bounds__(256) void gather_kernel(float* __restrict__ out)
{
    int n = blockIdx.x * 8 + (threadIdx.x >> 5);     // NN/8 = 6250 blocks, exact
    int lane = threadIdx.x & 31;
    int beg = g_off[n];
    int m   = g_cnt[n];

    float4 acc = make_float4(0.f, 0.f, 0.f, 0.f);
    const float* __restrict__ xt = g_xt;

    int j = 0;
    for (; j + 4 <= m; j += 4) {                     // 4 gathers in flight (MLP)
        int   c0 = g_col[beg + j],     c1 = g_col[beg + j + 1];
        int   c2 = g_col[beg + j + 2], c3 = g_col[beg + j + 3];
        float v0 = g_val[beg + j],     v1 = g_val[beg + j + 1];
        float v2 = g_val[beg + j + 2], v3 = g_val[beg + j + 3];
        float4 s0 = *(const float4*)(xt + (long)c0 * OC + lane * 4);
        float4 s1 = *(const float4*)(xt + (long)c1 * OC + lane * 4);
        float4 s2 = *(const float4*)(xt + (long)c2 * OC + lane * 4);
        float4 s3 = *(const float4*)(xt + (long)c3 * OC + lane * 4);
        acc.x += v0 * s0.x; acc.y += v0 * s0.y; acc.z += v0 * s0.z; acc.w += v0 * s0.w;
        acc.x += v1 * s1.x; acc.y += v1 * s1.y; acc.z += v1 * s1.z; acc.w += v1 * s1.w;
        acc.x += v2 * s2.x; acc.y += v2 * s2.y; acc.z += v2 * s2.z; acc.w += v2 * s2.w;
        acc.x += v3 * s3.x; acc.y += v3 * s3.y; acc.z += v3 * s3.z; acc.w += v3 * s3.w;
    }
    for (; j < m; j++) {
        int   c = g_col[beg + j];
        float v = g_val[beg + j];
        float4 s = *(const float4*)(xt + (long)c * OC + lane * 4);
        acc.x += v * s.x; acc.y += v * s.y; acc.z += v * s.z; acc.w += v * s.w;
    }

    int b = lane >> 4;                               // cols 0..63 -> b=0, 64..127 -> b=1
    float* op = out + ((long)b * NN + n) * FOUT + (lane & 15) * 4;
    float4 sc = *(float4*)op;
    sc.x = fmaxf(sc.x + acc.x, 0.f);
    sc.y = fmaxf(sc.y + acc.y, 0.f);
    sc.z = fmaxf(sc.z + acc.z, 0.f);
    sc.w = fmaxf(sc.w + acc.w, 0.f);
    *(float4*)op = sc;
}

extern "C" void kernel_launch(void* const* d_in, const int* in_sizes, int n_in,
                              void* d_out, int out_size)
{
    const float* x     = (const float*)d_in[0];
    const float* W     = (const float*)d_in[1];
    const float* Wself = (const float*)d_in[2];
    const float* bself = (const float*)d_in[3];
    const int*   erow  = (const int*)d_in[4];
    const int*   ecol  = (const int*)d_in[5];
    const float* eval  = (const float*)d_in[6];
    float* out = (float*)d_out;

    // One-time side stream + fork/join events (host objects, no device memory).
    static cudaStream_t sB = nullptr;
    static cudaEvent_t evFork = nullptr, evJoin = nullptr;
    if (sB == nullptr) {
        cudaStreamCreateWithFlags(&sB, cudaStreamNonBlocking);
        cudaEventCreateWithFlags(&evFork, cudaEventDisableTiming);
        cudaEventCreateWithFlags(&evJoin, cudaEventDisableTiming);
    }

    void* cntp = nullptr;
    cudaGetSymbolAddress(&cntp, g_cnt);

    // Fork: CSR build (depends only on edge arrays) runs on sB,
    // concurrently with the GEMM on the main stream.
    cudaEventRecord(evFork, 0);
    cudaStreamWaitEvent(sB, evFork, 0);

    cudaMemsetAsync(cntp, 0, (size_t)NN * sizeof(int), sB);
    hist_kernel<<<EE / 256, 256, 0, sB>>>(erow);
    scan_kernel<<<1, SCAN_T, 0, sB>>>();
    fill_kernel<<<EE / 256, 256, 0, sB>>>(erow, ecol, eval);
    cudaEventRecord(evJoin, sB);

    cudaFuncSetAttribute(gemm_kernel, cudaFuncAttributeMaxDynamicSharedMemorySize, WSM_BYTES);
    gemm_kernel<<<ROWS / 32, 128, WSM_BYTES>>>(x, W, Wself, bself, out);   // 3125 blocks

    // Join, then pull-gather (needs g_xt from gemm and CSR from sB).
    cudaStreamWaitEvent(0, evJoin, 0);
    gather_kernel<<<NN / 8, 256>>>(out);                               // 6250 blocks
}

// round 10
// speedup vs baseline: 1.2260x; 1.2260x over previous
#include <cuda_runtime.h>
#include <cstdint>

#define NN   50000
#define BB   2
#define FIN  128
#define FOUT 64
#define OC   128          // B*FOUT = gather row width
#define EE   800000
#define ROWS (BB * NN)    // 100000

#define WPAD 130          // padded f-stride, conflict-free LDS.64 (bank = (2c+f)%32, half-warp distinct)

// Scratch (allocation-free rule: __device__ globals)
__device__ float g_xt[NN * OC];   // x@W laid out as (n, b*FOUT + o)  -- gather source
__device__ float g_agg[NN * OC];  // scatter destination

// ---------------------------------------------------------------------------
// GEMM v4: column-split for occupancy.
// blockIdx.y = 0: cols = W (write g_xt), 1: cols = Wself (write out + bias).
// Block = 128 thr (4 warps x 8 rows = 32 rows). smem = 64 x WPAD transposed
// weight tile (33.3KB) -> 5 CTAs/SM (launch_bounds), ~31% occupancy.
// Lane owns cols {lane, 32+lane}; f-paired fp32x2 accumulators (no pack movs).
// ---------------------------------------------------------------------------
__global__ __launch_bounds__(128, 5) void gemm_kernel(
    const float* __restrict__ x, const float* __restrict__ W,
    const float* __restrict__ Wself, const float* __restrict__ bself,
    float* __restrict__ out)
{
    __shared__ float wsT[64 * WPAD];           // 33280 bytes
    const int t = threadIdx.x;
    const int path = blockIdx.y;               // 0: neighbor path, 1: self path
    const float* __restrict__ Wsrc = path ? Wself : W;

    for (int idx = t; idx < FIN * 64; idx += 128) {
        int f = idx >> 6, c = idx & 63;
        wsT[c * WPAD + f] = Wsrc[(f << 6) + c];
    }
    __syncthreads();

    const int lane = t & 31;
    long warp = (long)blockIdx.x * 4 + (t >> 5);
    long r0 = warp << 3;                       // 8 consecutive rows, same b (50000%8==0)
    const float* xp = x + r0 * FIN;

    unsigned long long acc[8][2];
    #pragma unroll
    for (int i = 0; i < 8; i++) { acc[i][0] = 0ull; acc[i][1] = 0ull; }

    const float* wp0 = wsT + lane * WPAD;
    const float* wp1 = wsT + (32 + lane) * WPAD;

    for (int f = 0; f < FIN; f += 4) {
        ulonglong2 xq[8];                      // two packed f-pairs per row (no movs)
        #pragma unroll
        for (int i = 0; i < 8; i++)
            xq[i] = *(const ulonglong2*)(xp + i * FIN + f);   // broadcast LDG.128

        unsigned long long w0A = *(const unsigned long long*)(wp0 + f);
        unsigned long long w0B = *(const unsigned long long*)(wp0 + f + 2);
        unsigned long long w1A = *(const unsigned long long*)(wp1 + f);
        unsigned long long w1B = *(const unsigned long long*)(wp1 + f + 2);

        #pragma unroll
        for (int i = 0; i < 8; i++) {
            asm("fma.rn.f32x2 %0, %1, %2, %0;" : "+l"(acc[i][0]) : "l"(xq[i].x), "l"(w0A));
            asm("fma.rn.f32x2 %0, %1, %2, %0;" : "+l"(acc[i][1]) : "l"(xq[i].x), "l"(w1A));
            asm("fma.rn.f32x2 %0, %1, %2, %0;" : "+l"(acc[i][0]) : "l"(xq[i].y), "l"(w0B));
            asm("fma.rn.f32x2 %0, %1, %2, %0;" : "+l"(acc[i][1]) : "l"(xq[i].y), "l"(w1B));
        }
    }

    int b  = (int)(r0 / NN);
    int n0 = (int)(r0 % NN);

    if (path == 0) {
        #pragma unroll
        for (int i = 0; i < 8; i++) {
            float lo0, hi0, lo1, hi1;
            asm("mov.b64 {%0, %1}, %2;" : "=f"(lo0), "=f"(hi0) : "l"(acc[i][0]));
            asm("mov.b64 {%0, %1}, %2;" : "=f"(lo1), "=f"(hi1) : "l"(acc[i][1]));
            float* xtp = g_xt + (long)(n0 + i) * OC + b * FOUT;
            xtp[lane]      = lo0 + hi0;
            xtp[32 + lane] = lo1 + hi1;
        }
    } else {
        const float b0 = bself[lane];
        const float b1 = bself[32 + lane];
        #pragma unroll
        for (int i = 0; i < 8; i++) {
            float lo0, hi0, lo1, hi1;
            asm("mov.b64 {%0, %1}, %2;" : "=f"(lo0), "=f"(hi0) : "l"(acc[i][0]));
            asm("mov.b64 {%0, %1}, %2;" : "=f"(lo1), "=f"(hi1) : "l"(acc[i][1]));
            float* op = out + ((long)b * NN + n0 + i) * FOUT;
            op[lane]      = lo0 + hi0 + b0;
            op[32 + lane] = lo1 + hi1 + b1;
        }
    }
}

// ---------------------------------------------------------------------------
// Edge scatter: one warp per edge. Lane l handles floats [4l,4l+4) of the
// 128-float row. Vector RED (red.global.add.v4.f32) quarters atomic op count.
// ---------------------------------------------------------------------------
__global__ __launch_bounds__(256) void scatter_kernel(
    const int* __restrict__ erow, const int* __restrict__ ecol,
    const float* __restrict__ eval)
{
    int e = blockIdx.x * 8 + (threadIdx.x >> 5);   // 800000 / 8 = 100000 blocks, exact
    int lane = threadIdx.x & 31;
    int r = erow[e], c = ecol[e];
    float v = eval[e];
    float4 s = *(const float4*)(g_xt + (long)c * OC + lane * 4);
    float* dst = g_agg + (long)r * OC + lane * 4;
    asm volatile("red.global.add.v4.f32 [%0], {%1, %2, %3, %4};"
                 :: "l"(dst), "f"(s.x * v), "f"(s.y * v), "f"(s.z * v), "f"(s.w * v)
                 : "memory");
}

// ---------------------------------------------------------------------------
// Epilogue: out[b][n][o] = relu(out[b][n][o] + agg[n][b*64+o])
// ---------------------------------------------------------------------------
__global__ __launch_bounds__(256) void epilogue_kernel(float* __restrict__ out)
{
    long i = (long)blockIdx.x * 256 + threadIdx.x;   // 1.6M float4 units, exact grid
    int  o4   = (int)(i & 15) * 4;
    long rest = i >> 4;                              // b*NN + n
    int  n = (int)(rest % NN);
    int  b = (int)(rest / NN);
    float4 a = *(const float4*)(g_agg + (long)n * OC + b * FOUT + o4);
    float4 s = *(float4*)(out + i * 4);
    s.x = fmaxf(s.x + a.x, 0.f);
    s.y = fmaxf(s.y + a.y, 0.f);
    s.z = fmaxf(s.z + a.z, 0.f);
    s.w = fmaxf(s.w + a.w, 0.f);
    *(float4*)(out + i * 4) = s;
}

extern "C" void kernel_launch(void* const* d_in, const int* in_sizes, int n_in,
                              void* d_out, int out_size)
{
    const float* x     = (const float*)d_in[0];
    const float* W     = (const float*)d_in[1];
    const float* Wself = (const float*)d_in[2];
    const float* bself = (const float*)d_in[3];
    const int*   erow  = (const int*)d_in[4];
    const int*   ecol  = (const int*)d_in[5];
    const float* eval  = (const float*)d_in[6];
    float* out = (float*)d_out;

    void* aggp = nullptr;
    cudaGetSymbolAddress(&aggp, g_agg);
    cudaMemsetAsync(aggp, 0, (size_t)NN * OC * sizeof(float), 0);

    dim3 ggrid(ROWS / 32, 2);
    gemm_kernel<<<ggrid, 128>>>(x, W, Wself, bself, out);              // 3125 x 2 blocks

    scatter_kernel<<<EE / 8, 256>>>(erow, ecol, eval);                 // 100000 blocks

    epilogue_kernel<<<(long)BB * NN * FOUT / 4 / 256, 256>>>(out);     // 6250 blocks
}

// round 12
// speedup vs baseline: 1.5406x; 1.2566x over previous
#include <cuda_runtime.h>
#include <cstdint>

#define NN   50000
#define BB   2
#define FIN  128
#define FOUT 64
#define OC   128          // B*FOUT = gather row width
#define EE   800000
#define ROWS (BB * NN)    // 100000

#define TILE_M 128
#define NT     128        // combined cols: 0..63 -> W -> g_xt, 64..127 -> Wself -> out
#define KHALF  64
#define STRIDE 72         // frag-row stride in floats; 36 = 4 (mod 16) -> conflict-free LDS.64

// smem float offsets
#define A_HI 0
#define A_LO (A_HI + TILE_M * STRIDE)      //  9216
#define B_HI (A_LO + TILE_M * STRIDE)      // 18432
#define B_LO (B_HI + NT * STRIDE)          // 27648
#define WPL  (B_LO + NT * STRIDE)          // 36864  plain W staging [64 f][128 n]
#define SM_FLOATS (WPL + KHALF * NT)       // 45056
#define SM_BYTES  (SM_FLOATS * 4)          // 180224

// Scratch (allocation-free rule: __device__ globals)
__device__ float g_xt[NN * OC];   // x@W laid out as (n, b*FOUT + o)  -- gather source
__device__ float g_agg[NN * OC];  // scatter destination

__device__ __forceinline__ uint32_t f2tf32(float f) {
    uint32_t u;
    asm("cvt.rna.tf32.f32 %0, %1;" : "=r"(u) : "f"(f));
    return u;
}
__device__ __forceinline__ void mma_tf32(float* d, uint32_t a0, uint32_t a1, uint32_t a2,
                                         uint32_t a3, uint32_t b0, uint32_t b1) {
    asm volatile(
        "mma.sync.aligned.m16n8k8.row.col.f32.tf32.tf32.f32 "
        "{%0,%1,%2,%3}, {%4,%5,%6,%7}, {%8,%9}, {%0,%1,%2,%3};"
        : "+f"(d[0]), "+f"(d[1]), "+f"(d[2]), "+f"(d[3])
        : "r"(a0), "r"(a1), "r"(a2), "r"(a3), "r"(b0), "r"(b1));
}

// k-permutation within each 8-group: pos p holds source q = (p&1)*4 + (p>>1).
// => (q, q+4) land at adjacent positions (2q, 2q+1): fragment pairs are LDS.64.

// ---------------------------------------------------------------------------
// 3xTF32 tensor GEMM: D[128r][128c] = x_tile @ [W | Wself]; K in two 64-halves.
// Warp w: rows 32*(w&3).., cols 64*(w>>2)..  (32x64 warp tile, 8 n-tiles).
// ---------------------------------------------------------------------------
__global__ __launch_bounds__(256, 1) void gemm_kernel(
    const float* __restrict__ x, const float* __restrict__ W,
    const float* __restrict__ Wself, const float* __restrict__ bself,
    float* __restrict__ out)
{
    extern __shared__ float sm[];
    const int t = threadIdx.x;
    const int w = t >> 5, lane = t & 31;
    const int g = lane >> 2, tg = lane & 3;
    const int p  = w & 3;          // m-pair (rows 32p..32p+31)
    const int nh = w >> 2;         // n-half (cols 64*nh..)
    const long rb = (long)blockIdx.x * TILE_M;

    float acc[2][8][4];
    #pragma unroll
    for (int ms = 0; ms < 2; ms++)
        #pragma unroll
        for (int nt = 0; nt < 8; nt++)
            #pragma unroll
            for (int e = 0; e < 4; e++) acc[ms][nt][e] = 0.f;

    #pragma unroll 1
    for (int h = 0; h < 2; h++) {
        // ---- stage A fragments (x tile, k-half h), hi+lo, permuted layout ----
        #pragma unroll
        for (int i = 0; i < 4; i++) {
            int v = i * 256 + t;
            int row = v & 127, c = v >> 7;           // c = k-step 0..7
            long gr = rb + row;
            float xv[8];
            if (gr < ROWS) {
                float4 u0 = *(const float4*)(x + gr * FIN + h * KHALF + c * 8);
                float4 u1 = *(const float4*)(x + gr * FIN + h * KHALF + c * 8 + 4);
                xv[0]=u0.x; xv[1]=u0.y; xv[2]=u0.z; xv[3]=u0.w;
                xv[4]=u1.x; xv[5]=u1.y; xv[6]=u1.z; xv[7]=u1.w;
            } else {
                #pragma unroll
                for (int q = 0; q < 8; q++) xv[q] = 0.f;
            }
            uint32_t hi[8], lo[8];
            #pragma unroll
            for (int q = 0; q < 8; q++) {
                hi[q] = f2tf32(xv[q]);
                lo[q] = f2tf32(xv[q] - __uint_as_float(hi[q]));
            }
            uint32_t* ah = (uint32_t*)(sm + A_HI + row * STRIDE + c * 8);
            uint32_t* al = (uint32_t*)(sm + A_LO + row * STRIDE + c * 8);
            // pos p <- q=(p&1)*4+(p>>1): [v0,v4,v1,v5][v2,v6,v3,v7]
            *(uint4*)ah       = make_uint4(hi[0], hi[4], hi[1], hi[5]);
            *(uint4*)(ah + 4) = make_uint4(hi[2], hi[6], hi[3], hi[7]);
            *(uint4*)al       = make_uint4(lo[0], lo[4], lo[1], lo[5]);
            *(uint4*)(al + 4) = make_uint4(lo[2], lo[6], lo[3], lo[7]);
        }
        // ---- stage plain weights for k-half: WPL[f_l][n] (n: 0..63 W, 64..127 Wself)
        #pragma unroll
        for (int i = 0; i < 8; i++) {
            int v = i * 256 + t;                     // 2048 float4 chunks
            int mat = v >> 10, rem = v & 1023;
            int fl = rem >> 4, o4 = (rem & 15) * 4;
            const float* src = (mat ? Wself : W) + (long)(h * KHALF + fl) * FOUT + o4;
            float4 u = *(const float4*)src;
            float* dst = sm + WPL + fl * NT + mat * 64 + o4;
            *(float4*)dst = u;
        }
        __syncthreads();
        // ---- build B fragments from WPL (transpose), hi+lo ----
        #pragma unroll
        for (int i = 0; i < 4; i++) {
            int v = i * 256 + t;
            int n = v & 127, s = v >> 7;             // s = k-step
            float wv[8];
            #pragma unroll
            for (int q = 0; q < 8; q++)
                wv[q] = sm[WPL + (s * 8 + q) * NT + n];   // bank = n%32: conflict-free
            uint32_t hi[8], lo[8];
            #pragma unroll
            for (int q = 0; q < 8; q++) {
                hi[q] = f2tf32(wv[q]);
                lo[q] = f2tf32(wv[q] - __uint_as_float(hi[q]));
            }
            uint32_t* bh = (uint32_t*)(sm + B_HI + n * STRIDE + s * 8);
            uint32_t* bl = (uint32_t*)(sm + B_LO + n * STRIDE + s * 8);
            *(uint4*)bh       = make_uint4(hi[0], hi[4], hi[1], hi[5]);
            *(uint4*)(bh + 4) = make_uint4(hi[2], hi[6], hi[3], hi[7]);
            *(uint4*)bl       = make_uint4(lo[0], lo[4], lo[1], lo[5]);
            *(uint4*)(bl + 4) = make_uint4(lo[2], lo[6], lo[3], lo[7]);
        }
        __syncthreads();

        // ---- main loop: 8 k-steps ----
        #pragma unroll
        for (int s = 0; s < 8; s++) {
            uint2 ah[2][2], al[2][2];   // [msub][row-half(g, g+8)] = (reg0, reg2)/(reg1, reg3)
            #pragma unroll
            for (int ms = 0; ms < 2; ms++) {
                int r0 = p * 32 + ms * 16 + g;
                ah[ms][0] = *(const uint2*)(sm + A_HI + r0 * STRIDE + s * 8 + 2 * tg);
                ah[ms][1] = *(const uint2*)(sm + A_HI + (r0 + 8) * STRIDE + s * 8 + 2 * tg);
                al[ms][0] = *(const uint2*)(sm + A_LO + r0 * STRIDE + s * 8 + 2 * tg);
                al[ms][1] = *(const uint2*)(sm + A_LO + (r0 + 8) * STRIDE + s * 8 + 2 * tg);
            }
            uint2 bh[8], bl[8];
            #pragma unroll
            for (int nt = 0; nt < 8; nt++) {
                int nr = nh * 64 + nt * 8 + g;
                bh[nt] = *(const uint2*)(sm + B_HI + nr * STRIDE + s * 8 + 2 * tg);
                bl[nt] = *(const uint2*)(sm + B_LO + nr * STRIDE + s * 8 + 2 * tg);
            }
            #pragma unroll
            for (int ms = 0; ms < 2; ms++) {
                // a regs: a0=pair0.x(row g,col tg) a1=pair1.x a2=pair0.y(col tg+4) a3=pair1.y
                #pragma unroll
                for (int nt = 0; nt < 8; nt++) {
                    float* d = acc[ms][nt];
                    mma_tf32(d, ah[ms][0].x, ah[ms][1].x, ah[ms][0].y, ah[ms][1].y,
                             bh[nt].x, bh[nt].y);                       // hi*hi
                    mma_tf32(d, ah[ms][0].x, ah[ms][1].x, ah[ms][0].y, ah[ms][1].y,
                             bl[nt].x, bl[nt].y);                       // hi*lo
                    mma_tf32(d, al[ms][0].x, al[ms][1].x, al[ms][0].y, al[ms][1].y,
                             bh[nt].x, bh[nt].y);                       // lo*hi
                }
            }
        }
        __syncthreads();
    }

    // ---- epilogue: direct float2 stores ----
    #pragma unroll
    for (int ms = 0; ms < 2; ms++) {
        #pragma unroll
        for (int nt = 0; nt < 8; nt++) {
            int col = nh * 64 + nt * 8 + 2 * tg;
            long r0 = rb + p * 32 + ms * 16 + g;
            long r1 = r0 + 8;
            float2 v0 = make_float2(acc[ms][nt][0], acc[ms][nt][1]);
            float2 v1 = make_float2(acc[ms][nt][2], acc[ms][nt][3]);
            if (nh == 0) {          // neighbor path -> g_xt[(n)*128 + b*64 + col]
                if (r0 < ROWS) {
                    int b = (int)(r0 / NN), n = (int)(r0 % NN);
                    *(float2*)(g_xt + (long)n * OC + b * FOUT + col) = v0;
                }
                if (r1 < ROWS) {
                    int b = (int)(r1 / NN), n = (int)(r1 % NN);
                    *(float2*)(g_xt + (long)n * OC + b * FOUT + col) = v1;
                }
            } else {                // self path -> out + bias
                int oc = col - 64;
                float2 bv = *(const float2*)(bself + oc);
                v0.x += bv.x; v0.y += bv.y;
                v1.x += bv.x; v1.y += bv.y;
                if (r0 < ROWS) *(float2*)(out + r0 * FOUT + oc) = v0;
                if (r1 < ROWS) *(float2*)(out + r1 * FOUT + oc) = v1;
            }
        }
    }
}

// ---------------------------------------------------------------------------
// Edge scatter: one warp per edge; vector RED into g_agg. (R6 path, measured.)
// ---------------------------------------------------------------------------
__global__ __launch_bounds__(256) void scatter_kernel(
    const int* __restrict__ erow, const int* __restrict__ ecol,
    const float* __restrict__ eval)
{
    int e = blockIdx.x * 8 + (threadIdx.x >> 5);   // 800000 / 8 = 100000 blocks, exact
    int lane = threadIdx.x & 31;
    int r = erow[e], c = ecol[e];
    float v = eval[e];
    float4 s = *(const float4*)(g_xt + (long)c * OC + lane * 4);
    float* dst = g_agg + (long)r * OC + lane * 4;
    asm volatile("red.global.add.v4.f32 [%0], {%1, %2, %3, %4};"
                 :: "l"(dst), "f"(s.x * v), "f"(s.y * v), "f"(s.z * v), "f"(s.w * v)
                 : "memory");
}

// ---------------------------------------------------------------------------
// Final epilogue: out[b][n][o] = relu(out[b][n][o] + agg[n][b*64+o])
// ---------------------------------------------------------------------------
__global__ __launch_bounds__(256) void epilogue_kernel(float* __restrict__ out)
{
    long i = (long)blockIdx.x * 256 + threadIdx.x;   // 1.6M float4 units, exact grid
    int  o4   = (int)(i & 15) * 4;
    long rest = i >> 4;                              // b*NN + n
    int  n = (int)(rest % NN);
    int  b = (int)(rest / NN);
    float4 a = *(const float4*)(g_agg + (long)n * OC + b * FOUT + o4);
    float4 s = *(float4*)(out + i * 4);
    s.x = fmaxf(s.x + a.x, 0.f);
    s.y = fmaxf(s.y + a.y, 0.f);
    s.z = fmaxf(s.z + a.z, 0.f);
    s.w = fmaxf(s.w + a.w, 0.f);
    *(float4*)(out + i * 4) = s;
}

extern "C" void kernel_launch(void* const* d_in, const int* in_sizes, int n_in,
                              void* d_out, int out_size)
{
    const float* x     = (const float*)d_in[0];
    const float* W     = (const float*)d_in[1];
    const float* Wself = (const float*)d_in[2];
    const float* bself = (const float*)d_in[3];
    const int*   erow  = (const int*)d_in[4];
    const int*   ecol  = (const int*)d_in[5];
    const float* eval  = (const float*)d_in[6];
    float* out = (float*)d_out;

    void* aggp = nullptr;
    cudaGetSymbolAddress(&aggp, g_agg);
    cudaMemsetAsync(aggp, 0, (size_t)NN * OC * sizeof(float), 0);

    cudaFuncSetAttribute(gemm_kernel, cudaFuncAttributeMaxDynamicSharedMemorySize, SM_BYTES);
    int gblocks = (ROWS + TILE_M - 1) / TILE_M;                        // 782
    gemm_kernel<<<gblocks, 256, SM_BYTES>>>(x, W, Wself, bself, out);

    scatter_kernel<<<EE / 8, 256>>>(erow, ecol, eval);                 // 100000 blocks

    epilogue_kernel<<<(long)BB * NN * FOUT / 4 / 256, 256>>>(out);     // 6250 blocks
}